// round 6
// baseline (speedup 1.0000x reference)
#include <cuda_runtime.h>
#include <cuda_fp16.h>
#include <stdint.h>

// Problem constants
#define Q_I     512
#define Q_O     32
#define Q_JD    8                  // dense degree slots (j=1..8; j=0 folded into bias)
#define Q_CHI   16                 // inputs per chunk
#define Q_CHK   128                // k per chunk (16*8) -> 8 k16 MMA steps
#define Q_NCH   32                 // 512/16
#define Q_ROWS  128                // batch rows per CTA
#define Q_THR   128                // 4 warps

// smem (halves): W [32][136] then basisT [128][136]
#define WPAD    136
#define BPAD    136
#define SM_W    0
#define SM_B    (Q_O * WPAD * 2)                  // 8704 bytes
#define SM_TOT  (SM_B + Q_CHK * BPAD * 2)         // 43520 bytes

// Repacked fp16 weights (j=1..8): g_W2[c][o][kl], kl = ip*8 + (j-1)
__device__ __half g_W2[Q_NCH * Q_O * Q_CHK];
__device__ float  g_bias[Q_O];

__global__ void repack_kernel(const float* __restrict__ w) {
    int idx = blockIdx.x * blockDim.x + threadIdx.x;
    if (idx >= Q_NCH * Q_O * Q_CHK) return;
    int kl = idx & 127;
    int o  = (idx >> 7) & 31;
    int c  = idx >> 12;
    int i  = c * Q_CHI + (kl >> 3);
    int j  = (kl & 7) + 1;
    g_W2[idx] = __float2half(w[(i * Q_O + o) * 9 + j]);
}

__global__ void bias_kernel(const float* __restrict__ w) {
    int o = threadIdx.x;              // 32 threads
    float s = 0.0f;
    for (int i = 0; i < Q_I; ++i) s += w[(i * Q_O + o) * 9];
    g_bias[o] = s;
}

// ---------------- primitives ----------------
__device__ __forceinline__ uint32_t smem_u32(const void* p) {
    uint32_t a;
    asm("{ .reg .u64 t; cvta.to.shared.u64 t, %1; cvt.u32.u64 %0, t; }" : "=r"(a) : "l"(p));
    return a;
}
__device__ __forceinline__ void ldm_x4(uint32_t (&r)[4], uint32_t addr) {
    asm volatile("ldmatrix.sync.aligned.m8n8.x4.shared.b16 {%0,%1,%2,%3}, [%4];"
                 : "=r"(r[0]), "=r"(r[1]), "=r"(r[2]), "=r"(r[3]) : "r"(addr));
}
__device__ __forceinline__ void ldm_x4_t(uint32_t (&r)[4], uint32_t addr) {
    asm volatile("ldmatrix.sync.aligned.m8n8.x4.trans.shared.b16 {%0,%1,%2,%3}, [%4];"
                 : "=r"(r[0]), "=r"(r[1]), "=r"(r[2]), "=r"(r[3]) : "r"(addr));
}
__device__ __forceinline__ void mma16816(float (&d)[4], const uint32_t (&a)[4],
                                         uint32_t b0, uint32_t b1) {
    asm volatile(
        "mma.sync.aligned.m16n8k16.row.col.f32.f16.f16.f32 "
        "{%0,%1,%2,%3}, {%4,%5,%6,%7}, {%8,%9}, {%0,%1,%2,%3};"
        : "+f"(d[0]), "+f"(d[1]), "+f"(d[2]), "+f"(d[3])
        : "r"(a[0]), "r"(a[1]), "r"(a[2]), "r"(a[3]), "r"(b0), "r"(b1));
}
__device__ __forceinline__ uint32_t pack2(float a, float b) {
    __half2 h = __floats2half2_rn(a, b);
    return *reinterpret_cast<uint32_t*>(&h);
}
// tanh(x) = 1 - 2/(exp2(2x*log2e)+1)
__device__ __forceinline__ float ftanh(float x) {
    float p;
    asm("ex2.approx.f32 %0, %1;" : "=f"(p) : "f"(x * 2.8853900817779268f));
    float r;
    asm("rcp.approx.f32 %0, %1;" : "=f"(r) : "f"(p + 1.0f));
    return fmaf(-2.0f, r, 1.0f);
}

__global__ __launch_bounds__(Q_THR)
void cheby_mma_kernel(const float* __restrict__ x, float* __restrict__ out) {
    extern __shared__ char smem[];
    const uint32_t sW = smem_u32(smem) + SM_W;
    const uint32_t sB = smem_u32(smem) + SM_B;

    const int t    = threadIdx.x;
    const int lane = t & 31;
    const int w    = t >> 5;             // warp id: rows [32w, 32w+32)
    const int b0   = blockIdx.x * Q_ROWS;

    // gen mapping (R4): thread owns row-pair (2rp, 2rp+1), inputs [ig*8, ig*8+8)
    const int rp = t & 63;
    const int ig = t >> 6;

    // ldmatrix lane address components
    const int g = lane >> 3, l = lane & 7;
    const int oRow = (g & 1) * 8 + l;
    const int kHlf = (g >> 1) * 8;
    const uint32_t wAddrBase = sW + (uint32_t)(oRow * WPAD + kHlf) * 2u;
    const int kOff = (g >> 1) * 8 + l;
    const int mOff = (g & 1) * 8;
    const uint32_t bAddrBase = sB + (uint32_t)(kOff * BPAD + w * 32 + mOff) * 2u;

    float acc[2][4][4];
#pragma unroll
    for (int ot = 0; ot < 2; ++ot)
#pragma unroll
        for (int rt = 0; rt < 4; ++rt)
#pragma unroll
            for (int q = 0; q < 4; ++q) acc[ot][rt][q] = 0.0f;

    // x pointers for this thread's row-pair, 8-input group
    const float* xr0 = x + (size_t)(b0 + 2 * rp) * Q_I + ig * 8;
    const float* xr1 = xr0 + Q_I;

    // ---- prefetch chunk 0 (x: 32B per row; W: 4 x uint4, coalesced) ----
    float4 xp0[2], xp1[2];
    uint4  wp[4];
    xp0[0] = *reinterpret_cast<const float4*>(xr0);
    xp0[1] = *reinterpret_cast<const float4*>(xr0 + 4);
    xp1[0] = *reinterpret_cast<const float4*>(xr1);
    xp1[1] = *reinterpret_cast<const float4*>(xr1 + 4);
#pragma unroll
    for (int q = 0; q < 4; ++q)
        wp[q] = *reinterpret_cast<const uint4*>(g_W2 + (q * 128 + t) * 8);

    for (int c = 0; c < Q_NCH; ++c) {
        if (c) __syncthreads();          // mma(c-1) finished reading smem

        // ---- stage W chunk from prefetched regs ----
#pragma unroll
        for (int q = 0; q < 4; ++q) {
            int flat = q * 128 + t;
            int o = flat >> 4, seg = flat & 15;
            asm volatile("st.shared.v4.b32 [%0], {%1,%2,%3,%4};"
                         :: "r"(sW + (uint32_t)(o * WPAD + seg * 8) * 2u),
                            "r"(wp[q].x), "r"(wp[q].y), "r"(wp[q].z), "r"(wp[q].w));
        }

        // ---- generate basis tile: 8 inputs x (j=1..8), half2 per row-pair ----
        {
            float xa[8], xb[8];
            *reinterpret_cast<float4*>(&xa[0]) = xp0[0];
            *reinterpret_cast<float4*>(&xa[4]) = xp0[1];
            *reinterpret_cast<float4*>(&xb[0]) = xp1[0];
            *reinterpret_cast<float4*>(&xb[4]) = xp1[1];
#pragma unroll
            for (int p = 0; p < 8; ++p) {
                float t0 = ftanh(xa[p]);
                float t1 = ftanh(xb[p]);
                float x20 = t0 + t0, x21 = t1 + t1;
                float a0 = 1.0f, b0v = 1.0f;   // U0 (not stored)
                float a1 = x20, b1v = x21;     // U1
                uint32_t ad = sB + (uint32_t)(((ig * 8 + p) * Q_JD) * (BPAD * 2)) + (uint32_t)(rp * 4);
#pragma unroll
                for (int j = 1; j <= 8; ++j) {
                    asm volatile("st.shared.b32 [%0], %1;" :: "r"(ad), "r"(pack2(a1, b1v)));
                    ad += BPAD * 2;
                    if (j < 8) {
                        float a2 = fmaf(x20, a1, -a0);
                        float b2 = fmaf(x21, b1v, -b0v);
                        a0 = a1; a1 = a2; b0v = b1v; b1v = b2;
                    }
                }
            }
        }
        __syncthreads();

        // ---- prefetch chunk c+1 (LDG latency hidden under MMA) ----
        if (c + 1 < Q_NCH) {
            const float* x0 = xr0 + (c + 1) * Q_CHI;
            const float* x1 = xr1 + (c + 1) * Q_CHI;
            xp0[0] = *reinterpret_cast<const float4*>(x0);
            xp0[1] = *reinterpret_cast<const float4*>(x0 + 4);
            xp1[0] = *reinterpret_cast<const float4*>(x1);
            xp1[1] = *reinterpret_cast<const float4*>(x1 + 4);
            const __half* wg = g_W2 + (size_t)(c + 1) * (Q_O * Q_CHK);
#pragma unroll
            for (int q = 0; q < 4; ++q)
                wp[q] = *reinterpret_cast<const uint4*>(wg + (q * 128 + t) * 8);
        }

        // ---- MMA: 8 k16-steps ----
        uint32_t wAddr = wAddrBase;
        uint32_t bAddr = bAddrBase;
#pragma unroll
        for (int ks = 0; ks < 8; ++ks) {
            uint32_t aW0[4], aW1[4], bb0[4], bb1[4];
            ldm_x4(aW0, wAddr);                       // o 0..15
            ldm_x4(aW1, wAddr + 16u * WPAD * 2u);     // o 16..31
            ldm_x4_t(bb0, bAddr);                     // rows m0..m0+15
            ldm_x4_t(bb1, bAddr + 32u);               // rows m0+16..m0+31
            mma16816(acc[0][0], aW0, bb0[0], bb0[2]);
            mma16816(acc[1][0], aW1, bb0[0], bb0[2]);
            mma16816(acc[0][1], aW0, bb0[1], bb0[3]);
            mma16816(acc[1][1], aW1, bb0[1], bb0[3]);
            mma16816(acc[0][2], aW0, bb1[0], bb1[2]);
            mma16816(acc[1][2], aW1, bb1[0], bb1[2]);
            mma16816(acc[0][3], aW0, bb1[1], bb1[3]);
            mma16816(acc[1][3], aW1, bb1[1], bb1[3]);
            wAddr += 32u;                 // +16 halves along k
            bAddr += 16u * BPAD * 2u;     // +16 k-rows
        }
    }

    // ---- epilogue: add bias, store ----
    const int qr = lane >> 2;
    const int qc = (lane & 3) * 2;
    float bo[2][2];
#pragma unroll
    for (int ot = 0; ot < 2; ++ot) {
        bo[ot][0] = g_bias[ot * 16 + qr];
        bo[ot][1] = g_bias[ot * 16 + qr + 8];
    }
#pragma unroll
    for (int rt = 0; rt < 4; ++rt) {
        int r = b0 + 32 * w + 8 * rt + qc;
        float* po0 = out + (size_t)r * Q_O;
        float* po1 = out + (size_t)(r + 1) * Q_O;
#pragma unroll
        for (int ot = 0; ot < 2; ++ot) {
            int o = ot * 16 + qr;
            po0[o]     = acc[ot][rt][0] + bo[ot][0];
            po1[o]     = acc[ot][rt][1] + bo[ot][0];
            po0[o + 8] = acc[ot][rt][2] + bo[ot][1];
            po1[o + 8] = acc[ot][rt][3] + bo[ot][1];
        }
    }
}

extern "C" void kernel_launch(void* const* d_in, const int* in_sizes, int n_in,
                              void* d_out, int out_size) {
    const float* x  = (const float*)d_in[0];     // [65536, 512] f32
    const float* wc = (const float*)d_in[1];     // [512, 32, 9] f32
    float* out = (float*)d_out;                  // [65536, 32] f32

    int Brows = in_sizes[0] / Q_I;

    int wtot = Q_NCH * Q_O * Q_CHK;              // 131072
    repack_kernel<<<(wtot + 255) / 256, 256>>>(wc);
    bias_kernel<<<1, Q_O>>>(wc);

    cheby_mma_kernel<<<Brows / Q_ROWS, Q_THR, SM_TOT>>>(x, out);
}